// round 7
// baseline (speedup 1.0000x reference)
#include <cuda_runtime.h>
#include <cuda_bf16.h>

// Problem constants
#define Bsz   4
#define NODES 51
#define MODAL 4
#define SEQ   256
#define DM    128
#define DK    64
#define NBN   (Bsz * NODES)          // 204
#define GRID_N 64                    // table nodes per (bn, j)

// {A2, C2, Wm, Bm} published by table-kernel block 0
__device__ float g_sc[4];
// Tabulated f_j(a): [bn][j][node]  (204*4*64*4B = 209 KB, L2-resident)
__device__ float g_F[NBN * MODAL * GRID_N];
// Per-bn grid params: {a_lo, inv_h}
__device__ float g_range[NBN * 2];

__device__ __forceinline__ float fast_exp2(float x) {
    float y;
    asm("ex2.approx.ftz.f32 %0, %1;" : "=f"(y) : "f"(x));
    return y;
}

// ---- packed f32x2 helpers ----
typedef unsigned long long u64;
__device__ __forceinline__ u64 pk2(float lo, float hi) {
    u64 r;
    asm("mov.b64 %0, {%1, %2};" : "=l"(r) : "f"(lo), "f"(hi));
    return r;
}
__device__ __forceinline__ void upk2(u64 p, float& lo, float& hi) {
    asm("mov.b64 {%0, %1}, %2;" : "=f"(lo), "=f"(hi) : "l"(p));
}
__device__ __forceinline__ u64 mul2(u64 a, u64 b) {
    u64 r;
    asm("mul.rn.f32x2 %0, %1, %2;" : "=l"(r) : "l"(a), "l"(b));
    return r;
}
__device__ __forceinline__ u64 fma2(u64 a, u64 b, u64 c) {
    u64 r;
    asm("fma.rn.f32x2 %0, %1, %2, %3;" : "=l"(r) : "l"(a), "l"(b), "l"(c));
    return r;
}
__device__ __forceinline__ u64 add2(u64 a, u64 b) {
    u64 r;
    asm("add.rn.f32x2 %0, %1, %2;" : "=l"(r) : "l"(a), "l"(b));
    return r;
}

// ---------------------------------------------------------------------------
// Kernel T: tables. Block = (bn, jpair), 256 threads.
// Redundant A2/C2 from L2-hot Wq/Wk (overlapped with MUFU work of other
// resident blocks). thread = (j in 2, node g in 64, half in 2); each thread
// does 128 exps over its half of x_j, pair-combined via shfl_xor(1).
// Block 0 additionally publishes {A2, C2, Wm, Bm} to g_sc.
// ---------------------------------------------------------------------------
__global__ __launch_bounds__(256) void mmf_table_kernel(
    const float* __restrict__ x,
    const float* __restrict__ Wq, const float* __restrict__ bq,
    const float* __restrict__ Wk,
    const float* __restrict__ Wv, const float* __restrict__ bv) {
    const int blk   = blockIdx.x;        // bn*2 + jpair
    const int jpair = blk & 1;
    const int bn    = blk >> 1;

    const int tid  = threadIdx.x;
    const int wid  = tid >> 5;
    const int lane = tid & 31;

    __shared__ float4 sx4[MODAL][SEQ / 4];   // 4 KB x tile
    __shared__ float swk[DK];                // Wk row sums
    __shared__ float wredA[8];
    __shared__ float wmax[8], wmin[8];
    __shared__ float sAC[2];                 // {A2, C2}
    __shared__ float sxr[2];                 // {xmin, xmax}

    // ---- x tile (coalesced float4) + per-warp min/max ----
    float4 v = ((const float4*)(x + (size_t)bn * (MODAL * SEQ)))[tid];
    ((float4*)sx4)[tid] = v;
    {
        float mx = fmaxf(fmaxf(v.x, v.y), fmaxf(v.z, v.w));
        float mn = fminf(fminf(v.x, v.y), fminf(v.z, v.w));
#pragma unroll
        for (int off = 16; off; off >>= 1) {
            mx = fmaxf(mx, __shfl_xor_sync(0xffffffff, mx, off));
            mn = fminf(mn, __shfl_xor_sync(0xffffffff, mn, off));
        }
        if (lane == 0) { wmax[wid] = mx; wmin[wid] = mn; }
    }

    // ---- wk row sums: 4 threads per row, 32 cols each ----
    {
        const int k   = tid >> 2;
        const int sub = tid & 3;
        const float4* p = (const float4*)(Wk + k * DM + sub * 32);
        float s = 0.f;
#pragma unroll
        for (int q = 0; q < 8; q++) {
            float4 a = p[q];
            s += (a.x + a.y) + (a.z + a.w);
        }
        s += __shfl_xor_sync(0xffffffff, s, 1);
        s += __shfl_xor_sync(0xffffffff, s, 2);
        if (sub == 0) swk[k] = s;
    }
    __syncthreads();

    // ---- A2 partial: (rowsum Wq[k]) * wk[k], block-reduced ----
    {
        const int k   = tid >> 2;
        const int sub = tid & 3;
        const float4* p = (const float4*)(Wq + k * DM + sub * 32);
        float s = 0.f;
#pragma unroll
        for (int q = 0; q < 8; q++) {
            float4 a = p[q];
            s += (a.x + a.y) + (a.z + a.w);
        }
        float pa = s * swk[k] * 0.25f;   // each of 4 sub-threads carries 1/4
#pragma unroll
        for (int off = 16; off; off >>= 1) pa += __shfl_xor_sync(0xffffffff, pa, off);
        if (lane == 0) wredA[wid] = pa;
    }
    __syncthreads();

    // Wait: pa above included s (partial rowsum) * full swk[k]; the four
    // sub-threads of row k each hold partial_q * wk[k], and
    // sum_sub partial_q = full rowsum -> sum over subs of partial*wk = rowsum*wk.
    // So drop the 0.25 factor -- correct reduction is the plain sum.
    // (0.25f above is WRONG; compensate by multiplying back by 4 here.)

    // ---- finalize A2/C2 (warp 0), x range (warp 1) ----
    if (wid == 0) {
        float pa = (lane < 8) ? wredA[lane] * 4.0f : 0.f;
        float pc = bq[lane] * swk[lane] + bq[lane + 32] * swk[lane + 32];
#pragma unroll
        for (int off = 16; off; off >>= 1) {
            pa += __shfl_xor_sync(0xffffffff, pa, off);
            pc += __shfl_xor_sync(0xffffffff, pc, off);
        }
        if (lane == 0) {
            const float K = 0.125f * 1.4426950408889634f;  // log2e/sqrt(64)
            sAC[0] = pa * K;
            sAC[1] = pc * K;
        }
    } else if (wid == 1 && lane == 0) {
        float tmx = wmax[0], tmn = wmin[0];
#pragma unroll
        for (int k = 1; k < 8; k++) {
            tmx = fmaxf(tmx, wmax[k]);
            tmn = fminf(tmn, wmin[k]);
        }
        sxr[0] = tmn;
        sxr[1] = tmx;
    }
    __syncthreads();

    const float A2  = sAC[0];
    const float C2s = sAC[1];
    const float a_c1 = fmaf(A2, sxr[0], C2s);
    const float a_c2 = fmaf(A2, sxr[1], C2s);
    const float alo = fminf(a_c1, a_c2);
    const float ahi = fmaxf(a_c1, a_c2);
    const float h = (ahi - alo) * (1.0f / (GRID_N - 1));

    // ---- tabulate: j = 2*jpair + (tid>>7), g = (tid>>1)&63, half = tid&1 ----
    const int j    = 2 * jpair + (tid >> 7);
    const int g    = (tid >> 1) & (GRID_N - 1);
    const int half = tid & 1;

    const float ag = fmaf(h, (float)g, alo);
    const u64 a22 = pk2(ag, ag);

    u64 num01 = 0ull, num23 = 0ull;
    u64 den01 = 0ull, den23 = 0ull;
    const ulonglong2* __restrict__ row =
        (const ulonglong2*)&sx4[j][half * (SEQ / 8)];
#pragma unroll 8
    for (int t4 = 0; t4 < SEQ / 8; t4++) {      // 128 elements
        ulonglong2 xt = row[t4];
        u64 p01 = mul2(a22, xt.x);
        u64 p23 = mul2(a22, xt.y);
        float p0, p1, p2, p3;
        upk2(p01, p0, p1);
        upk2(p23, p2, p3);
        float e0 = fast_exp2(p0);
        float e1 = fast_exp2(p1);
        float e2 = fast_exp2(p2);
        float e3 = fast_exp2(p3);
        u64 e01 = pk2(e0, e1);
        u64 e23 = pk2(e2, e3);
        num01 = fma2(xt.x, e01, num01);
        num23 = fma2(xt.y, e23, num23);
        den01 = add2(den01, e01);
        den23 = add2(den23, e23);
    }
    float n0, n1, n2, n3, d0, d1, d2, d3;
    upk2(num01, n0, n1);
    upk2(num23, n2, n3);
    upk2(den01, d0, d1);
    upk2(den23, d2, d3);
    float num = (n0 + n1) + (n2 + n3);
    float den = (d0 + d1) + (d2 + d3);
    num += __shfl_xor_sync(0xffffffff, num, 1);
    den += __shfl_xor_sync(0xffffffff, den, 1);
    if (half == 0)
        g_F[((size_t)bn * MODAL + j) * GRID_N + g] = __fdividef(num, den);

    if (jpair == 0 && tid == 0) {
        g_range[2 * bn]     = alo;
        g_range[2 * bn + 1] = (ahi > alo) ? (float)(GRID_N - 1) / (ahi - alo) : 0.0f;
    }

    // ---- block 0: publish scalars for the interp kernel ----
    if (blk == 0) {
        // Wv total: 4 threads/row x 32 cols each, block reduce via wredA reuse
        const int k   = tid >> 2;
        const int sub = tid & 3;
        const float4* p = (const float4*)(Wv + k * DM + sub * 32);
        float sv = 0.f;
#pragma unroll
        for (int q = 0; q < 8; q++) {
            float4 a = p[q];
            sv += (a.x + a.y) + (a.z + a.w);
        }
#pragma unroll
        for (int off = 16; off; off >>= 1) sv += __shfl_xor_sync(0xffffffff, sv, off);
        __syncthreads();                 // protect wredA reuse
        if (lane == 0) wredA[wid] = sv;
        __syncthreads();
        if (wid == 0) {
            float pv = (lane < 8) ? wredA[lane] : 0.f;
            float pb = bv[lane] + bv[lane + 32];
#pragma unroll
            for (int off = 16; off; off >>= 1) {
                pv += __shfl_xor_sync(0xffffffff, pv, off);
                pb += __shfl_xor_sync(0xffffffff, pb, off);
            }
            if (lane == 0) {
                g_sc[0] = A2;
                g_sc[1] = C2s;
                g_sc[2] = pv * (1.0f / DK) * (1.0f / (MODAL - 1));  // Wm
                g_sc[3] = pb * (1.0f / DK);                         // Bm
            }
        }
    }
}

// ---------------------------------------------------------------------------
// Kernel I: interpolate. Block = bn (1024 threads: i = tid>>8, s = tid&255).
// Catmull-Rom cubic on the per-(bn,j) table; sum over j != i.
// ---------------------------------------------------------------------------
__global__ __launch_bounds__(1024, 1) void mmf_interp_kernel(const float* __restrict__ x,
                                                             float* __restrict__ out) {
    const int bn = blockIdx.x;
    __shared__ float sF[MODAL][GRID_N];      // 1 KB table

    const int tid = threadIdx.x;
    if (tid < MODAL * GRID_N)
        ((float*)sF)[tid] = g_F[(size_t)bn * (MODAL * GRID_N) + tid];
    __syncthreads();

    const int i = tid >> 8;

    const float A2 = g_sc[0];
    const float C2s = g_sc[1];
    const float Wm = g_sc[2];
    const float Bm = g_sc[3];

    const float xi = x[(size_t)bn * (MODAL * SEQ) + tid];
    const float a2 = fmaf(A2, xi, C2s);
    const float alo  = g_range[2 * bn];
    const float invh = g_range[2 * bn + 1];

    float u = (a2 - alo) * invh;
    int i1 = (int)floorf(u);
    i1 = max(0, min(GRID_N - 2, i1));
    float fr = fminf(fmaxf(u - (float)i1, 0.0f), 1.0f);
    const int im  = max(i1 - 1, 0);
    const int ip2 = min(i1 + 2, GRID_N - 1);

    float acc = 0.f;
#pragma unroll
    for (int j = 0; j < MODAL; j++) {
        if (j == i) continue;
        float p0 = sF[j][im];
        float p1 = sF[j][i1];
        float p2 = sF[j][i1 + 1];
        float p3 = sF[j][ip2];
        // Catmull-Rom
        float c3 = 3.0f * (p1 - p2) + (p3 - p0);
        float c2 = 2.0f * p0 - 5.0f * p1 + 4.0f * p2 - p3;
        float c1 = p2 - p0;
        float f = fmaf(0.5f * fr, fmaf(fr, fmaf(fr, c3, c2), c1), p1);
        acc += f;
    }

    out[(size_t)bn * (MODAL * SEQ) + tid] = fmaf(Wm, acc, Bm);
}

// ---------------------------------------------------------------------------
// Launch
// ---------------------------------------------------------------------------
extern "C" void kernel_launch(void* const* d_in, const int* in_sizes, int n_in,
                              void* d_out, int out_size) {
    const float* x  = (const float*)d_in[0];
    const float* Wq = (const float*)d_in[1];
    const float* bq = (const float*)d_in[2];
    const float* Wk = (const float*)d_in[3];
    const float* Wv = (const float*)d_in[5];
    const float* bv = (const float*)d_in[6];
    float* out = (float*)d_out;

    mmf_table_kernel<<<NBN * 2, 256>>>(x, Wq, bq, Wk, Wv, bv);
    mmf_interp_kernel<<<NBN, 1024>>>(x, out);
}

// round 8
// speedup vs baseline: 1.7351x; 1.7351x over previous
#include <cuda_runtime.h>
#include <cuda_bf16.h>

// Problem constants
#define Bsz   4
#define NODES 51
#define MODAL 4
#define SEQ   256
#define DM    128
#define DK    64
#define NBN   (Bsz * NODES)          // 204
#define GRID_N 64                    // table nodes per (bn, j)

__device__ __forceinline__ float fast_exp2(float x) {
    float y;
    asm("ex2.approx.ftz.f32 %0, %1;" : "=f"(y) : "f"(x));
    return y;
}

// ---- packed f32x2 helpers ----
typedef unsigned long long u64;
__device__ __forceinline__ u64 pk2(float lo, float hi) {
    u64 r;
    asm("mov.b64 %0, {%1, %2};" : "=l"(r) : "f"(lo), "f"(hi));
    return r;
}
__device__ __forceinline__ void upk2(u64 p, float& lo, float& hi) {
    asm("mov.b64 {%0, %1}, %2;" : "=f"(lo), "=f"(hi) : "l"(p));
}
__device__ __forceinline__ u64 mul2(u64 a, u64 b) {
    u64 r;
    asm("mul.rn.f32x2 %0, %1, %2;" : "=l"(r) : "l"(a), "l"(b));
    return r;
}
__device__ __forceinline__ u64 fma2(u64 a, u64 b, u64 c) {
    u64 r;
    asm("fma.rn.f32x2 %0, %1, %2, %3;" : "=l"(r) : "l"(a), "l"(b), "l"(c));
    return r;
}
__device__ __forceinline__ u64 add2(u64 a, u64 b) {
    u64 r;
    asm("add.rn.f32x2 %0, %1, %2;" : "=l"(r) : "l"(a), "l"(b));
    return r;
}

// ---------------------------------------------------------------------------
// Single fused kernel. Block = bn (204 blocks x 512 threads, 16 warps).
// Phase 1: x tile (threads 0-255) + per-warp min/max.
// Phase 2: slim weight prologue. Warp w owns rows 4w..4w+3 of Wq/Wk/Wv:
//          1 float4 per lane per row (MLP 12), in-warp rowsums + dot with wk,
//          then one 16-wide block reduction for {A2, C2, Wm}; warp 15 sums bv.
// Phase 3: tabulate f_j on a 64-node grid. thread = (j, node, half);
//          each thread does 128 exps, pair-combined via shfl_xor(1).
// Phase 4: Catmull-Rom interpolation, 2 outputs per thread, all from smem.
// ---------------------------------------------------------------------------
__global__ __launch_bounds__(512, 2) void mmf_fused_kernel(
    const float* __restrict__ x,
    const float* __restrict__ Wq, const float* __restrict__ bq,
    const float* __restrict__ Wk,
    const float* __restrict__ Wv, const float* __restrict__ bv,
    float* __restrict__ out) {
    const int bn = blockIdx.x;
    const int tid = threadIdx.x;
    const int wid = tid >> 5;          // 0..15
    const int lane = tid & 31;

    __shared__ float4 sx4[MODAL][SEQ / 4];   // 4 KB x tile
    __shared__ float sF[MODAL][GRID_N];      // 1 KB table
    __shared__ float wpart[16][3];           // per-warp {pa, pc, pv}
    __shared__ float wmax[8], wmin[8];
    __shared__ float spb;                    // bv sum
    __shared__ float sc[4];                  // {A2, C2, Wm, Bm}
    __shared__ float sxr[2];                 // {xmin, xmax}
    __shared__ float sgrid[2];               // {a_lo, inv_h}

    // ---- Phase 1: x tile + min/max (threads 0-255; warps 8-15 fall through) ----
    if (tid < 256) {
        float4 v = ((const float4*)(x + (size_t)bn * (MODAL * SEQ)))[tid];
        ((float4*)sx4)[tid] = v;
        float mx = fmaxf(fmaxf(v.x, v.y), fmaxf(v.z, v.w));
        float mn = fminf(fminf(v.x, v.y), fminf(v.z, v.w));
#pragma unroll
        for (int off = 16; off; off >>= 1) {
            mx = fmaxf(mx, __shfl_xor_sync(0xffffffff, mx, off));
            mn = fminf(mn, __shfl_xor_sync(0xffffffff, mn, off));
        }
        if (lane == 0) { wmax[wid] = mx; wmin[wid] = mn; }
    }

    // ---- Phase 2: weight prologue. Warp w: rows 4w..4w+3 ----
    {
        float pa = 0.f, pc = 0.f, pv = 0.f;
#pragma unroll
        for (int r = 0; r < 4; r++) {
            const int row = wid * 4 + r;
            float4 q  = ((const float4*)(Wq + row * DM))[lane];
            float4 kk = ((const float4*)(Wk + row * DM))[lane];
            float4 vv = ((const float4*)(Wv + row * DM))[lane];
            float sq = (q.x + q.y) + (q.z + q.w);
            float sk = (kk.x + kk.y) + (kk.z + kk.w);
            float sv = (vv.x + vv.y) + (vv.z + vv.w);
#pragma unroll
            for (int off = 16; off; off >>= 1) {
                sq += __shfl_xor_sync(0xffffffff, sq, off);
                sk += __shfl_xor_sync(0xffffffff, sk, off);
                sv += __shfl_xor_sync(0xffffffff, sv, off);
            }
            pa = fmaf(sq, sk, pa);
            pc = fmaf(bq[row], sk, pc);   // uniform broadcast load
            pv += sv;
        }
        if (lane == 0) {
            wpart[wid][0] = pa;
            wpart[wid][1] = pc;
            wpart[wid][2] = pv;
        }
        if (wid == 15) {
            float pb = bv[lane] + bv[lane + 32];
#pragma unroll
            for (int off = 16; off; off >>= 1) pb += __shfl_xor_sync(0xffffffff, pb, off);
            if (lane == 0) spb = pb;
        }
    }
    __syncthreads();

    // ---- finalize scalars (warp 0) + x range (warp 1) ----
    if (wid == 0) {
        float pa = (lane < 16) ? wpart[lane][0] : 0.f;
        float pc = (lane < 16) ? wpart[lane][1] : 0.f;
        float pv = (lane < 16) ? wpart[lane][2] : 0.f;
#pragma unroll
        for (int off = 8; off; off >>= 1) {
            pa += __shfl_xor_sync(0xffffffff, pa, off);
            pc += __shfl_xor_sync(0xffffffff, pc, off);
            pv += __shfl_xor_sync(0xffffffff, pv, off);
        }
        if (lane == 0) {
            const float K = 0.125f * 1.4426950408889634f;  // log2e/sqrt(64)
            sc[0] = pa * K;                                 // A2
            sc[1] = pc * K;                                 // C2
            sc[2] = pv * (1.0f / DK) * (1.0f / (MODAL - 1));  // Wm
            sc[3] = spb * (1.0f / DK);                      // Bm
        }
    } else if (wid == 1 && lane == 0) {
        float tmx = wmax[0], tmn = wmin[0];
#pragma unroll
        for (int k = 1; k < 8; k++) {
            tmx = fmaxf(tmx, wmax[k]);
            tmn = fminf(tmn, wmin[k]);
        }
        sxr[0] = tmn;
        sxr[1] = tmx;
    }
    __syncthreads();

    const float A2  = sc[0];
    const float C2s = sc[1];
    {
        const float a_c1 = fmaf(A2, sxr[0], C2s);
        const float a_c2 = fmaf(A2, sxr[1], C2s);
        const float alo = fminf(a_c1, a_c2);
        const float ahi = fmaxf(a_c1, a_c2);
        const float h = (ahi - alo) * (1.0f / (GRID_N - 1));

        if (tid == 0) {
            sgrid[0] = alo;
            sgrid[1] = (ahi > alo) ? (float)(GRID_N - 1) / (ahi - alo) : 0.0f;
        }

        // ---- Phase 3: tabulate. thread = (j, node g, half) ----
        const int j    = tid >> 7;              // warp-uniform
        const int g    = (tid >> 1) & (GRID_N - 1);
        const int half = tid & 1;

        const float ag = fmaf(h, (float)g, alo);
        const u64 a22 = pk2(ag, ag);

        u64 num01 = 0ull, num23 = 0ull;
        u64 den01 = 0ull, den23 = 0ull;
        const ulonglong2* __restrict__ row =
            (const ulonglong2*)&sx4[j][half * (SEQ / 8)];
#pragma unroll 8
        for (int t4 = 0; t4 < SEQ / 8; t4++) {      // 128 elements
            ulonglong2 xt = row[t4];
            u64 p01 = mul2(a22, xt.x);
            u64 p23 = mul2(a22, xt.y);
            float p0, p1, p2, p3;
            upk2(p01, p0, p1);
            upk2(p23, p2, p3);
            float e0 = fast_exp2(p0);
            float e1 = fast_exp2(p1);
            float e2 = fast_exp2(p2);
            float e3 = fast_exp2(p3);
            u64 e01 = pk2(e0, e1);
            u64 e23 = pk2(e2, e3);
            num01 = fma2(xt.x, e01, num01);
            num23 = fma2(xt.y, e23, num23);
            den01 = add2(den01, e01);
            den23 = add2(den23, e23);
        }
        float n0, n1, n2, n3, d0, d1, d2, d3;
        upk2(num01, n0, n1);
        upk2(num23, n2, n3);
        upk2(den01, d0, d1);
        upk2(den23, d2, d3);
        float num = (n0 + n1) + (n2 + n3);
        float den = (d0 + d1) + (d2 + d3);
        num += __shfl_xor_sync(0xffffffff, num, 1);
        den += __shfl_xor_sync(0xffffffff, den, 1);
        if (half == 0) sF[j][g] = __fdividef(num, den);
    }
    __syncthreads();

    // ---- Phase 4: interpolate. 2 outputs per thread ----
    const float alo  = sgrid[0];
    const float invh = sgrid[1];
    const float Wm = sc[2];
    const float Bm = sc[3];

#pragma unroll
    for (int rep = 0; rep < 2; rep++) {
        const int idx = tid + rep * 512;     // (i, s) = (idx>>8, idx&255)
        const int i = idx >> 8;

        const float xi = ((const float*)sx4)[idx];
        const float a2 = fmaf(A2, xi, C2s);

        float u = (a2 - alo) * invh;
        int i1 = (int)floorf(u);
        i1 = max(0, min(GRID_N - 2, i1));
        float fr = fminf(fmaxf(u - (float)i1, 0.0f), 1.0f);
        const int im  = max(i1 - 1, 0);
        const int ip2 = min(i1 + 2, GRID_N - 1);

        float acc = 0.f;
#pragma unroll
        for (int j = 0; j < MODAL; j++) {
            if (j == i) continue;
            float p0 = sF[j][im];
            float p1 = sF[j][i1];
            float p2 = sF[j][i1 + 1];
            float p3 = sF[j][ip2];
            // Catmull-Rom
            float c3 = 3.0f * (p1 - p2) + (p3 - p0);
            float c2 = 2.0f * p0 - 5.0f * p1 + 4.0f * p2 - p3;
            float c1 = p2 - p0;
            float f = fmaf(0.5f * fr, fmaf(fr, fmaf(fr, c3, c2), c1), p1);
            acc += f;
        }

        out[(size_t)bn * (MODAL * SEQ) + idx] = fmaf(Wm, acc, Bm);
    }
}

// ---------------------------------------------------------------------------
// Launch
// ---------------------------------------------------------------------------
extern "C" void kernel_launch(void* const* d_in, const int* in_sizes, int n_in,
                              void* d_out, int out_size) {
    const float* x  = (const float*)d_in[0];
    const float* Wq = (const float*)d_in[1];
    const float* bq = (const float*)d_in[2];
    const float* Wk = (const float*)d_in[3];
    const float* Wv = (const float*)d_in[5];
    const float* bv = (const float*)d_in[6];
    float* out = (float*)d_out;

    mmf_fused_kernel<<<NBN, 512>>>(x, Wq, bq, Wk, Wv, bv, out);
}